// round 1
// baseline (speedup 1.0000x reference)
#include <cuda_runtime.h>
#include <math.h>

#define N_PTS 2000000
#define N_CLU 65536

// Scratch (device globals: allocation-free per harness rules)
__device__ float g_agg[N_CLU * 64];    // segment-sum accumulator [C,64]
__device__ float g_mid[N_CLU * 128];   // hidden of output MLP [C,128]

__device__ __forceinline__ float f4get(float4 v, int r) {
    return r == 0 ? v.x : (r == 1 ? v.y : (r == 2 ? v.z : v.w));
}

// ---------------------------------------------------------------------------
// Kernel 0: zero the aggregation buffer
// ---------------------------------------------------------------------------
__global__ void k_zero() {
    int i = blockIdx.x * 256 + threadIdx.x;
    if (i < N_CLU * 64) g_agg[i] = 0.0f;
}

// ---------------------------------------------------------------------------
// Kernel 1: per-point edge MLP + attention + scatter-add into g_agg
// 2 points per thread (halves weight-LDS per FMA). Weights staged in SMEM.
// ---------------------------------------------------------------------------
__global__ __launch_bounds__(256) void k_point(
    const float* __restrict__ pf, const int* __restrict__ labels,
    const float* __restrict__ cc, const float* __restrict__ pts,
    const float* __restrict__ we0, const float* __restrict__ be0,
    const float* __restrict__ we1, const float* __restrict__ be1,
    const float* __restrict__ we2, const float* __restrict__ be2,
    const float* __restrict__ we3, const float* __restrict__ be3,
    const float* __restrict__ wa0, const float* __restrict__ ba0,
    const float* __restrict__ wa1, const float* __restrict__ ba1)
{
    __shared__ float s[3744];
    float* sWE0 = s + 0;     // 88
    float* sBE0 = s + 88;    // 8
    float* sWE1 = s + 96;    // 128
    float* sBE1 = s + 224;   // 16
    float* sWE2 = s + 240;   // 512
    float* sBE2 = s + 752;   // 32
    float* sWE3 = s + 784;   // 2048
    float* sBE3 = s + 2832;  // 64
    float* sWA0 = s + 2896;  // 704
    float* sBA0 = s + 3600;  // 64
    float* sWA1 = s + 3664;  // 64
    float* sBA1 = s + 3728;  // 1

    const int t = threadIdx.x;
    for (int i = t; i < 88; i += 256)   sWE0[i] = we0[i];
    if (t < 8)                          sBE0[t] = be0[t];
    for (int i = t; i < 128; i += 256)  sWE1[i] = we1[i];
    if (t < 16)                         sBE1[t] = be1[t];
    for (int i = t; i < 512; i += 256)  sWE2[i] = we2[i];
    if (t < 32)                         sBE2[t] = be2[t];
    for (int i = t; i < 2048; i += 256) sWE3[i] = we3[i];
    if (t < 64)                         sBE3[t] = be3[t];
    for (int i = t; i < 704; i += 256)  sWA0[i] = wa0[i];
    if (t < 64)                         sBA0[t] = ba0[t];
    if (t < 64)                         sWA1[t] = wa1[t];
    if (t == 0)                         sBA1[0] = ba1[0];
    __syncthreads();

    const int i0 = blockIdx.x * 512 + t;

    float x[2][11];
    int   lbl[2];
    bool  ok[2];

#pragma unroll
    for (int p = 0; p < 2; p++) {
        int i = i0 + p * 256;
        ok[p] = (i < N_PTS);
        int ii = ok[p] ? i : 0;
        const float4* pf4 = (const float4*)(pf + (size_t)ii * 8);
        float4 v0 = pf4[0];
        float4 v1 = pf4[1];
        x[p][0] = v0.x; x[p][1] = v0.y; x[p][2] = v0.z; x[p][3] = v0.w;
        x[p][4] = v1.x; x[p][5] = v1.y; x[p][6] = v1.z; x[p][7] = v1.w;
        int l = labels[ii];
        lbl[p] = l;
#pragma unroll
        for (int k = 0; k < 3; k++)
            x[p][8 + k] = cc[(size_t)l * 3 + k] - pts[(size_t)ii * 3 + k];
    }

    // ----- attention: a = sigmoid( relu(x@wa0+ba0) @ wa1 + ba1 ) -----
    float aa0 = sBA1[0];
    float aa1 = aa0;
#pragma unroll 8
    for (int j = 0; j < 64; j++) {
        float t0 = sBA0[j];
        float t1 = t0;
#pragma unroll
        for (int k = 0; k < 11; k++) {
            float w = sWA0[k * 64 + j];
            t0 = fmaf(x[0][k], w, t0);
            t1 = fmaf(x[1][k], w, t1);
        }
        t0 = fmaxf(t0, 0.0f);
        t1 = fmaxf(t1, 0.0f);
        float w1 = sWA1[j];
        aa0 = fmaf(t0, w1, aa0);
        aa1 = fmaf(t1, w1, aa1);
    }
    float a0 = 1.0f / (1.0f + expf(-aa0));
    float a1 = 1.0f / (1.0f + expf(-aa1));

    // ----- edge MLP -----
    float h0[2][8];
#pragma unroll
    for (int j = 0; j < 8; j++) {
        float c0 = sBE0[j], c1 = c0;
#pragma unroll
        for (int k = 0; k < 11; k++) {
            float w = sWE0[k * 8 + j];
            c0 = fmaf(x[0][k], w, c0);
            c1 = fmaf(x[1][k], w, c1);
        }
        h0[0][j] = fmaxf(c0, 0.0f);
        h0[1][j] = fmaxf(c1, 0.0f);
    }

    float h1[2][16];
#pragma unroll
    for (int j = 0; j < 16; j++) {
        float c0 = sBE1[j], c1 = c0;
#pragma unroll
        for (int k = 0; k < 8; k++) {
            float w = sWE1[k * 16 + j];
            c0 = fmaf(h0[0][k], w, c0);
            c1 = fmaf(h0[1][k], w, c1);
        }
        h1[0][j] = fmaxf(c0, 0.0f);
        h1[1][j] = fmaxf(c1, 0.0f);
    }

    float h2[2][32];
#pragma unroll
    for (int j = 0; j < 32; j++) {
        float c0 = sBE2[j], c1 = c0;
#pragma unroll
        for (int k = 0; k < 16; k++) {
            float w = sWE2[k * 32 + j];
            c0 = fmaf(h1[0][k], w, c0);
            c1 = fmaf(h1[1][k], w, c1);
        }
        h2[0][j] = fmaxf(c0, 0.0f);
        h2[1][j] = fmaxf(c1, 0.0f);
    }

    // ----- layer 3 streamed: h3_j = relu(...); scatter t_j = h3_j * a -----
    float* agg0 = g_agg + (size_t)lbl[0] * 64;
    float* agg1 = g_agg + (size_t)lbl[1] * 64;
#pragma unroll 4
    for (int j = 0; j < 64; j++) {
        float c0 = sBE3[j], c1 = c0;
#pragma unroll
        for (int k = 0; k < 32; k++) {
            float w = sWE3[k * 64 + j];
            c0 = fmaf(h2[0][k], w, c0);
            c1 = fmaf(h2[1][k], w, c1);
        }
        c0 = fmaxf(c0, 0.0f) * a0;
        c1 = fmaxf(c1, 0.0f) * a1;
        if (ok[0]) atomicAdd(agg0 + j, c0);
        if (ok[1]) atomicAdd(agg1 + j, c1);
    }
}

// ---------------------------------------------------------------------------
// Kernel 2: g_mid = relu(g_agg @ wo0 + bo0)   [C,64] -> [C,128]
// 8 clusters per block of 256 threads; wo0 (32KB) staged in SMEM.
// ---------------------------------------------------------------------------
__global__ __launch_bounds__(256) void k_mid(
    const float* __restrict__ wo0, const float* __restrict__ bo0)
{
    __shared__ float sw[64 * 128];
    __shared__ float sb[128];
    __shared__ __align__(16) float sagg[8 * 64];

    const int t  = threadIdx.x;
    const int cb = blockIdx.x * 8;

    for (int i = t; i < 8192; i += 256) sw[i] = wo0[i];
    if (t < 128) sb[t] = bo0[t];
    for (int i = t; i < 512; i += 256) sagg[i] = g_agg[(size_t)cb * 64 + i];
    __syncthreads();

    const int j  = t & 127;
    const int cg = t >> 7;  // 0/1 -> clusters cg*4 .. cg*4+3

    float acc[4];
#pragma unroll
    for (int i = 0; i < 4; i++) acc[i] = sb[j];

    const float4* a4[4];
#pragma unroll
    for (int i = 0; i < 4; i++)
        a4[i] = (const float4*)(sagg + (cg * 4 + i) * 64);

#pragma unroll
    for (int k4 = 0; k4 < 16; k4++) {
        float4 m[4];
#pragma unroll
        for (int i = 0; i < 4; i++) m[i] = a4[i][k4];
#pragma unroll
        for (int r = 0; r < 4; r++) {
            float w = sw[(k4 * 4 + r) * 128 + j];
#pragma unroll
            for (int i = 0; i < 4; i++)
                acc[i] = fmaf(f4get(m[i], r), w, acc[i]);
        }
    }

#pragma unroll
    for (int i = 0; i < 4; i++)
        g_mid[(size_t)(cb + cg * 4 + i) * 128 + j] = fmaxf(acc[i], 0.0f);
}

// ---------------------------------------------------------------------------
// Kernel 3: out = relu(g_mid @ wo1 + bo1)   [C,128] -> [C,256]
// 8 clusters per block of 256 threads; wo1 (128KB) streamed in 32KB chunks.
// ---------------------------------------------------------------------------
__global__ __launch_bounds__(256) void k_out(
    const float* __restrict__ wo1, const float* __restrict__ bo1,
    float* __restrict__ out)
{
    __shared__ float sw[32 * 256];                  // 32 KB
    __shared__ __align__(16) float smid[8 * 128];   // 4 KB

    const int t  = threadIdx.x;
    const int cb = blockIdx.x * 8;

    for (int i = t; i < 1024; i += 256) {
        int c = i >> 7;
        smid[i] = g_mid[(size_t)(cb + c) * 128 + (i & 127)];
    }

    float acc[8];
    float b = bo1[t];
#pragma unroll
    for (int c = 0; c < 8; c++) acc[c] = b;

    for (int kb = 0; kb < 4; kb++) {
        __syncthreads();  // protect sw from previous iteration / smid on first
        for (int i = t; i < 8192; i += 256) sw[i] = wo1[kb * 8192 + i];
        __syncthreads();

#pragma unroll
        for (int k4 = 0; k4 < 8; k4++) {
            float4 m[8];
#pragma unroll
            for (int c = 0; c < 8; c++)
                m[c] = *(const float4*)(smid + c * 128 + kb * 32 + k4 * 4);
#pragma unroll
            for (int r = 0; r < 4; r++) {
                float w = sw[(k4 * 4 + r) * 256 + t];
#pragma unroll
                for (int c = 0; c < 8; c++)
                    acc[c] = fmaf(f4get(m[c], r), w, acc[c]);
            }
        }
    }

#pragma unroll
    for (int c = 0; c < 8; c++)
        out[(size_t)(cb + c) * 256 + t] = fmaxf(acc[c], 0.0f);
}

// ---------------------------------------------------------------------------
extern "C" void kernel_launch(void* const* d_in, const int* in_sizes, int n_in,
                              void* d_out, int out_size)
{
    const float* pf     = (const float*)d_in[0];
    const int*   labels = (const int*)  d_in[1];
    const float* cc     = (const float*)d_in[2];
    const float* pts    = (const float*)d_in[3];
    const float* we0    = (const float*)d_in[4];
    const float* be0    = (const float*)d_in[5];
    const float* we1    = (const float*)d_in[6];
    const float* be1    = (const float*)d_in[7];
    const float* we2    = (const float*)d_in[8];
    const float* be2    = (const float*)d_in[9];
    const float* we3    = (const float*)d_in[10];
    const float* be3    = (const float*)d_in[11];
    const float* wa0    = (const float*)d_in[12];
    const float* ba0    = (const float*)d_in[13];
    const float* wa1    = (const float*)d_in[14];
    const float* ba1    = (const float*)d_in[15];
    const float* wo0    = (const float*)d_in[16];
    const float* bo0    = (const float*)d_in[17];
    const float* wo1    = (const float*)d_in[18];
    const float* bo1    = (const float*)d_in[19];
    float* out = (float*)d_out;

    k_zero<<<(N_CLU * 64 + 255) / 256, 256>>>();
    k_point<<<(N_PTS + 511) / 512, 256>>>(pf, labels, cc, pts,
                                          we0, be0, we1, be1, we2, be2, we3, be3,
                                          wa0, ba0, wa1, ba1);
    k_mid<<<N_CLU / 8, 256>>>(wo0, bo0);
    k_out<<<N_CLU / 8, 256>>>(wo1, bo1, out);
}

// round 2
// speedup vs baseline: 1.2100x; 1.2100x over previous
#include <cuda_runtime.h>
#include <math.h>
#include <stdint.h>

#define N_PTS 2000000
#define N_CLU 65536

// Scratch (device globals: allocation-free per harness rules)
__device__ float g_agg[N_CLU * 64];     // segment-sum accumulator [C,64]
__device__ float g_mid[N_CLU * 128];    // blocked: [cgroup=c/16][k=0..127][c%16]

// ---------------------------------------------------------------------------
// packed f32x2 helpers (Blackwell native)
// ---------------------------------------------------------------------------
__device__ __forceinline__ uint64_t pack2(float lo, float hi) {
    uint64_t r; asm("mov.b64 %0,{%1,%2};" : "=l"(r) : "f"(lo), "f"(hi)); return r;
}
__device__ __forceinline__ float2 unpack2(uint64_t v) {
    float2 r; asm("mov.b64 {%0,%1},%2;" : "=f"(r.x), "=f"(r.y) : "l"(v)); return r;
}
__device__ __forceinline__ uint64_t fma2(uint64_t a, uint64_t b, uint64_t c) {
    uint64_t d; asm("fma.rn.f32x2 %0,%1,%2,%3;" : "=l"(d) : "l"(a), "l"(b), "l"(c)); return d;
}
__device__ __forceinline__ uint64_t mul2(uint64_t a, uint64_t b) {
    uint64_t d; asm("mul.rn.f32x2 %0,%1,%2;" : "=l"(d) : "l"(a), "l"(b)); return d;
}
__device__ __forceinline__ uint64_t relu2(uint64_t v) {
    float2 f = unpack2(v);
    return pack2(fmaxf(f.x, 0.0f), fmaxf(f.y, 0.0f));
}
__device__ __forceinline__ void red4(float* p, float a, float b, float c, float d) {
    asm volatile("red.global.add.v4.f32 [%0], {%1,%2,%3,%4};"
                 :: "l"(p), "f"(a), "f"(b), "f"(c), "f"(d) : "memory");
}

// ---------------------------------------------------------------------------
// Kernel 0: zero the aggregation buffer (float4 stores)
// ---------------------------------------------------------------------------
__global__ void k_zero() {
    int i = blockIdx.x * 256 + threadIdx.x;
    float4 z = make_float4(0.f, 0.f, 0.f, 0.f);
    ((float4*)g_agg)[i] = z;
}

// ---------------------------------------------------------------------------
// Kernel 1: per-point edge MLP + attention + vector scatter-add into g_agg
// 2 points per thread packed into f32x2 lanes. Weights duplicated in SMEM so
// one broadcast LDS.64 feeds one FFMA2.
// ---------------------------------------------------------------------------
__global__ __launch_bounds__(256) void k_point(
    const float* __restrict__ pf, const int* __restrict__ labels,
    const float* __restrict__ cc, const float* __restrict__ pts,
    const float* __restrict__ we0, const float* __restrict__ be0,
    const float* __restrict__ we1, const float* __restrict__ be1,
    const float* __restrict__ we2, const float* __restrict__ be2,
    const float* __restrict__ we3, const float* __restrict__ be3,
    const float* __restrict__ wa0, const float* __restrict__ ba0,
    const float* __restrict__ wa1, const float* __restrict__ ba1)
{
    __shared__ uint64_t s[3729];
    uint64_t* sWE0 = s + 0;     // 88
    uint64_t* sBE0 = s + 88;    // 8
    uint64_t* sWE1 = s + 96;    // 128
    uint64_t* sBE1 = s + 224;   // 16
    uint64_t* sWE2 = s + 240;   // 512
    uint64_t* sBE2 = s + 752;   // 32
    uint64_t* sWE3 = s + 784;   // 2048
    uint64_t* sBE3 = s + 2832;  // 64
    uint64_t* sWA0 = s + 2896;  // 704
    uint64_t* sBA0 = s + 3600;  // 64
    uint64_t* sWA1 = s + 3664;  // 64
    uint64_t* sBA1 = s + 3728;  // 1

    const int t = threadIdx.x;
    {
        // duplicate each weight/bias into both f32x2 halves
        #define DUP(dst, src, n) for (int i = t; i < (n); i += 256) { float v = (src)[i]; (dst)[i] = pack2(v, v); }
        DUP(sWE0, we0, 88)  DUP(sBE0, be0, 8)
        DUP(sWE1, we1, 128) DUP(sBE1, be1, 16)
        DUP(sWE2, we2, 512) DUP(sBE2, be2, 32)
        DUP(sWE3, we3, 2048) DUP(sBE3, be3, 64)
        DUP(sWA0, wa0, 704) DUP(sBA0, ba0, 64)
        DUP(sWA1, wa1, 64)  DUP(sBA1, ba1, 1)
        #undef DUP
    }
    __syncthreads();

    const int i0 = blockIdx.x * 512 + t;
    const int i1 = i0 + 256;
    const bool ok0 = (i0 < N_PTS);
    const bool ok1 = (i1 < N_PTS);
    const int ia = ok0 ? i0 : 0;
    const int ib = ok1 ? i1 : 0;

    // build packed input x2[k] = {x_point0[k], x_point1[k]}
    uint64_t x2[11];
    {
        const float4* pa = (const float4*)(pf + (size_t)ia * 8);
        const float4* pb = (const float4*)(pf + (size_t)ib * 8);
        float4 a0 = pa[0], a1 = pa[1], b0 = pb[0], b1 = pb[1];
        x2[0] = pack2(a0.x, b0.x); x2[1] = pack2(a0.y, b0.y);
        x2[2] = pack2(a0.z, b0.z); x2[3] = pack2(a0.w, b0.w);
        x2[4] = pack2(a1.x, b1.x); x2[5] = pack2(a1.y, b1.y);
        x2[6] = pack2(a1.z, b1.z); x2[7] = pack2(a1.w, b1.w);
    }
    const int l0 = labels[ia];
    const int l1 = labels[ib];
#pragma unroll
    for (int k = 0; k < 3; k++)
        x2[8 + k] = pack2(cc[(size_t)l0 * 3 + k] - pts[(size_t)ia * 3 + k],
                          cc[(size_t)l1 * 3 + k] - pts[(size_t)ib * 3 + k]);

    // ----- attention: a = sigmoid( relu(x@wa0+ba0) @ wa1 + ba1 ) -----
    uint64_t aa = sBA1[0];
#pragma unroll 4
    for (int j = 0; j < 64; j++) {
        uint64_t c = sBA0[j];
#pragma unroll
        for (int k = 0; k < 11; k++) c = fma2(x2[k], sWA0[k * 64 + j], c);
        aa = fma2(relu2(c), sWA1[j], aa);
    }
    float2 av = unpack2(aa);
    float s0 = 1.0f / (1.0f + expf(-av.x));
    float s1 = 1.0f / (1.0f + expf(-av.y));
    uint64_t a2 = pack2(s0, s1);

    // ----- edge MLP -----
    uint64_t h0[8];
#pragma unroll
    for (int j = 0; j < 8; j++) {
        uint64_t c = sBE0[j];
#pragma unroll
        for (int k = 0; k < 11; k++) c = fma2(x2[k], sWE0[k * 8 + j], c);
        h0[j] = relu2(c);
    }
    uint64_t h1[16];
#pragma unroll
    for (int j = 0; j < 16; j++) {
        uint64_t c = sBE1[j];
#pragma unroll
        for (int k = 0; k < 8; k++) c = fma2(h0[k], sWE1[k * 16 + j], c);
        h1[j] = relu2(c);
    }
    uint64_t h2[32];
#pragma unroll
    for (int j = 0; j < 32; j++) {
        uint64_t c = sBE2[j];
#pragma unroll
        for (int k = 0; k < 16; k++) c = fma2(h1[k], sWE2[k * 32 + j], c);
        h2[j] = relu2(c);
    }

    // ----- layer 3 streamed + vector scatter -----
    float* agg0 = g_agg + (size_t)l0 * 64;
    float* agg1 = g_agg + (size_t)l1 * 64;
#pragma unroll 2
    for (int j4 = 0; j4 < 16; j4++) {
        float r0[4], r1[4];
#pragma unroll
        for (int jj = 0; jj < 4; jj++) {
            int j = j4 * 4 + jj;
            uint64_t c = sBE3[j];
#pragma unroll
            for (int k = 0; k < 32; k++) c = fma2(h2[k], sWE3[k * 64 + j], c);
            c = mul2(relu2(c), a2);
            float2 f = unpack2(c);
            r0[jj] = f.x; r1[jj] = f.y;
        }
        if (ok0) red4(agg0 + j4 * 4, r0[0], r0[1], r0[2], r0[3]);
        if (ok1) red4(agg1 + j4 * 4, r1[0], r1[1], r1[2], r1[3]);
    }
}

// ---------------------------------------------------------------------------
// Kernel 2: g_mid = relu(g_agg @ wo0 + bo0), stored blocked [c/16][k][c%16]
// ---------------------------------------------------------------------------
__device__ __forceinline__ float f4get(float4 v, int r) {
    return r == 0 ? v.x : (r == 1 ? v.y : (r == 2 ? v.z : v.w));
}

__global__ __launch_bounds__(256) void k_mid(
    const float* __restrict__ wo0, const float* __restrict__ bo0)
{
    __shared__ float sw[64 * 128];
    __shared__ float sb[128];
    __shared__ __align__(16) float sagg[8 * 64];

    const int t  = threadIdx.x;
    const int cb = blockIdx.x * 8;

    for (int i = t; i < 8192; i += 256) sw[i] = wo0[i];
    if (t < 128) sb[t] = bo0[t];
    for (int i = t; i < 512; i += 256) sagg[i] = g_agg[(size_t)cb * 64 + i];
    __syncthreads();

    const int j  = t & 127;   // output dim index k of g_mid
    const int cg = t >> 7;    // 0/1 -> clusters cg*4 .. cg*4+3

    float acc[4];
#pragma unroll
    for (int i = 0; i < 4; i++) acc[i] = sb[j];

    const float4* a4[4];
#pragma unroll
    for (int i = 0; i < 4; i++)
        a4[i] = (const float4*)(sagg + (cg * 4 + i) * 64);

#pragma unroll
    for (int k4 = 0; k4 < 16; k4++) {
        float4 m[4];
#pragma unroll
        for (int i = 0; i < 4; i++) m[i] = a4[i][k4];
#pragma unroll
        for (int r = 0; r < 4; r++) {
            float w = sw[(k4 * 4 + r) * 128 + j];
#pragma unroll
            for (int i = 0; i < 4; i++)
                acc[i] = fmaf(f4get(m[i], r), w, acc[i]);
        }
    }

#pragma unroll
    for (int i = 0; i < 4; i++) {
        int c = cb + cg * 4 + i;
        g_mid[(size_t)(c >> 4) * 2048 + (size_t)j * 16 + (c & 15)] = fmaxf(acc[i], 0.0f);
    }
}

// ---------------------------------------------------------------------------
// Kernel 3: out = relu(g_mid @ wo1 + bo1)  [C,128] -> [C,256]
// 16 clusters per block as 8 packed cluster-pairs; f32x2 accumulators.
// ---------------------------------------------------------------------------
__global__ __launch_bounds__(256) void k_out(
    const float* __restrict__ wo1, const float* __restrict__ bo1,
    float* __restrict__ out)
{
    __shared__ float sw[32 * 256];                 // 32 KB weight chunk
    __shared__ __align__(16) uint64_t smid[128 * 8];  // [k][cpair] packed pairs

    const int t  = threadIdx.x;
    const int cg = blockIdx.x;          // group of 16 clusters

    // load this group's activations: g_mid blocked layout is already [k][16]
    const uint64_t* gm = (const uint64_t*)(g_mid + (size_t)cg * 2048);
    for (int i = t; i < 1024; i += 256) smid[i] = gm[i];

    uint64_t acc[8];
    {
        float b = bo1[t];
#pragma unroll
        for (int p = 0; p < 8; p++) acc[p] = pack2(b, b);
    }

    for (int kb = 0; kb < 4; kb++) {
        __syncthreads();
        for (int i = t; i < 8192; i += 256) sw[i] = wo1[kb * 8192 + i];
        __syncthreads();

#pragma unroll 8
        for (int k = 0; k < 32; k++) {
            float w = sw[k * 256 + t];
            uint64_t w2 = pack2(w, w);
            const uint64_t* mrow = smid + (kb * 32 + k) * 8;
#pragma unroll
            for (int p = 0; p < 8; p++)
                acc[p] = fma2(mrow[p], w2, acc[p]);
        }
    }

#pragma unroll
    for (int p = 0; p < 8; p++) {
        float2 f = unpack2(acc[p]);
        out[(size_t)(cg * 16 + 2 * p) * 256 + t]     = fmaxf(f.x, 0.0f);
        out[(size_t)(cg * 16 + 2 * p + 1) * 256 + t] = fmaxf(f.y, 0.0f);
    }
}

// ---------------------------------------------------------------------------
extern "C" void kernel_launch(void* const* d_in, const int* in_sizes, int n_in,
                              void* d_out, int out_size)
{
    const float* pf     = (const float*)d_in[0];
    const int*   labels = (const int*)  d_in[1];
    const float* cc     = (const float*)d_in[2];
    const float* pts    = (const float*)d_in[3];
    const float* we0    = (const float*)d_in[4];
    const float* be0    = (const float*)d_in[5];
    const float* we1    = (const float*)d_in[6];
    const float* be1    = (const float*)d_in[7];
    const float* we2    = (const float*)d_in[8];
    const float* be2    = (const float*)d_in[9];
    const float* we3    = (const float*)d_in[10];
    const float* be3    = (const float*)d_in[11];
    const float* wa0    = (const float*)d_in[12];
    const float* ba0    = (const float*)d_in[13];
    const float* wa1    = (const float*)d_in[14];
    const float* ba1    = (const float*)d_in[15];
    const float* wo0    = (const float*)d_in[16];
    const float* bo0    = (const float*)d_in[17];
    const float* wo1    = (const float*)d_in[18];
    const float* bo1    = (const float*)d_in[19];
    float* out = (float*)d_out;

    k_zero<<<N_CLU * 64 / 4 / 256, 256>>>();
    k_point<<<(N_PTS + 511) / 512, 256>>>(pf, labels, cc, pts,
                                          we0, be0, we1, be1, we2, be2, we3, be3,
                                          wa0, ba0, wa1, ba1);
    k_mid<<<N_CLU / 8, 256>>>(wo0, bo0);
    k_out<<<N_CLU / 16, 256>>>(wo1, bo1, out);
}

// round 3
// speedup vs baseline: 1.5716x; 1.2988x over previous
#include <cuda_runtime.h>
#include <math.h>
#include <stdint.h>

#define N_PTS 2000000
#define N_CLU 65536

__device__ float g_agg[N_CLU * 64];     // segment-sum accumulator [C,64]
__device__ float g_mid[N_CLU * 128];    // blocked: [c/16][k=0..127][c%16]

// ---------------------------------------------------------------------------
// packed f32x2 helpers
// ---------------------------------------------------------------------------
__device__ __forceinline__ uint64_t pack2(float lo, float hi) {
    uint64_t r; asm("mov.b64 %0,{%1,%2};" : "=l"(r) : "f"(lo), "f"(hi)); return r;
}
__device__ __forceinline__ float2 unpack2(uint64_t v) {
    float2 r; asm("mov.b64 {%0,%1},%2;" : "=f"(r.x), "=f"(r.y) : "l"(v)); return r;
}
__device__ __forceinline__ uint64_t fma2(uint64_t a, uint64_t b, uint64_t c) {
    uint64_t d; asm("fma.rn.f32x2 %0,%1,%2,%3;" : "=l"(d) : "l"(a), "l"(b), "l"(c)); return d;
}
__device__ __forceinline__ uint64_t mul2(uint64_t a, uint64_t b) {
    uint64_t d; asm("mul.rn.f32x2 %0,%1,%2;" : "=l"(d) : "l"(a), "l"(b)); return d;
}
__device__ __forceinline__ uint64_t relu2(uint64_t v) {
    float2 f = unpack2(v);
    return pack2(fmaxf(f.x, 0.0f), fmaxf(f.y, 0.0f));
}
__device__ __forceinline__ void red4(float* p, float a, float b, float c, float d) {
    asm volatile("red.global.add.v4.f32 [%0], {%1,%2,%3,%4};"
                 :: "l"(p), "f"(a), "f"(b), "f"(c), "f"(d) : "memory");
}

// ---------------------------------------------------------------------------
// Kernel 0: zero the aggregation buffer
// ---------------------------------------------------------------------------
__global__ void k_zero() {
    int i = blockIdx.x * 256 + threadIdx.x;
    ((float4*)g_agg)[i] = make_float4(0.f, 0.f, 0.f, 0.f);
}

// ---------------------------------------------------------------------------
// Kernel 1: per-point MLPs + scatter. 4 points/thread as two f32x2 pairs;
// every weight LDS.64 feeds two FFMA2.
// ---------------------------------------------------------------------------
__global__ __launch_bounds__(128) void k_point(
    const float* __restrict__ pf, const int* __restrict__ labels,
    const float* __restrict__ cc, const float* __restrict__ pts,
    const float* __restrict__ we0, const float* __restrict__ be0,
    const float* __restrict__ we1, const float* __restrict__ be1,
    const float* __restrict__ we2, const float* __restrict__ be2,
    const float* __restrict__ we3, const float* __restrict__ be3,
    const float* __restrict__ wa0, const float* __restrict__ ba0,
    const float* __restrict__ wa1, const float* __restrict__ ba1)
{
    __shared__ uint64_t s[3729];
    uint64_t* sWE0 = s + 0;     // 88
    uint64_t* sBE0 = s + 88;    // 8
    uint64_t* sWE1 = s + 96;    // 128
    uint64_t* sBE1 = s + 224;   // 16
    uint64_t* sWE2 = s + 240;   // 512
    uint64_t* sBE2 = s + 752;   // 32
    uint64_t* sWE3 = s + 784;   // 2048
    uint64_t* sBE3 = s + 2832;  // 64
    uint64_t* sWA0 = s + 2896;  // 704
    uint64_t* sBA0 = s + 3600;  // 64
    uint64_t* sWA1 = s + 3664;  // 64
    uint64_t* sBA1 = s + 3728;  // 1

    const int t = threadIdx.x;
    {
        #define DUP(dst, src, n) for (int i = t; i < (n); i += 128) { float v = (src)[i]; (dst)[i] = pack2(v, v); }
        DUP(sWE0, we0, 88)   DUP(sBE0, be0, 8)
        DUP(sWE1, we1, 128)  DUP(sBE1, be1, 16)
        DUP(sWE2, we2, 512)  DUP(sBE2, be2, 32)
        DUP(sWE3, we3, 2048) DUP(sBE3, be3, 64)
        DUP(sWA0, wa0, 704)  DUP(sBA0, ba0, 64)
        DUP(sWA1, wa1, 64)   DUP(sBA1, ba1, 1)
        #undef DUP
    }
    __syncthreads();

    const int base = blockIdx.x * 512 + t;
    int  idx[4];
    bool ok[4];
#pragma unroll
    for (int p = 0; p < 4; p++) {
        idx[p] = base + p * 128;
        ok[p]  = (idx[p] < N_PTS);
        if (!ok[p]) idx[p] = 0;
    }

    // pair q packs points (2q, 2q+1)
    uint64_t x2[2][11];
    int lbl[4];
#pragma unroll
    for (int q = 0; q < 2; q++) {
        int ia = idx[2 * q], ib = idx[2 * q + 1];
        const float4* pa = (const float4*)(pf + (size_t)ia * 8);
        const float4* pb = (const float4*)(pf + (size_t)ib * 8);
        float4 a0 = pa[0], a1 = pa[1], b0 = pb[0], b1 = pb[1];
        x2[q][0] = pack2(a0.x, b0.x); x2[q][1] = pack2(a0.y, b0.y);
        x2[q][2] = pack2(a0.z, b0.z); x2[q][3] = pack2(a0.w, b0.w);
        x2[q][4] = pack2(a1.x, b1.x); x2[q][5] = pack2(a1.y, b1.y);
        x2[q][6] = pack2(a1.z, b1.z); x2[q][7] = pack2(a1.w, b1.w);
        int la = labels[ia], lb = labels[ib];
        lbl[2 * q] = la; lbl[2 * q + 1] = lb;
#pragma unroll
        for (int k = 0; k < 3; k++)
            x2[q][8 + k] = pack2(cc[(size_t)la * 3 + k] - pts[(size_t)ia * 3 + k],
                                 cc[(size_t)lb * 3 + k] - pts[(size_t)ib * 3 + k]);
    }

    // ----- attention -----
    uint64_t aa0 = sBA1[0], aa1 = aa0;
#pragma unroll 2
    for (int j = 0; j < 64; j++) {
        uint64_t c0 = sBA0[j], c1 = c0;
#pragma unroll
        for (int k = 0; k < 11; k++) {
            uint64_t w = sWA0[k * 64 + j];
            c0 = fma2(x2[0][k], w, c0);
            c1 = fma2(x2[1][k], w, c1);
        }
        uint64_t w1 = sWA1[j];
        aa0 = fma2(relu2(c0), w1, aa0);
        aa1 = fma2(relu2(c1), w1, aa1);
    }
    uint64_t a2[2];
    {
        float2 v0 = unpack2(aa0), v1 = unpack2(aa1);
        a2[0] = pack2(1.0f / (1.0f + __expf(-v0.x)), 1.0f / (1.0f + __expf(-v0.y)));
        a2[1] = pack2(1.0f / (1.0f + __expf(-v1.x)), 1.0f / (1.0f + __expf(-v1.y)));
    }

    // ----- edge L0: 11 -> 8 -----
    uint64_t h0[2][8];
#pragma unroll
    for (int j = 0; j < 8; j++) {
        uint64_t c0 = sBE0[j], c1 = c0;
#pragma unroll
        for (int k = 0; k < 11; k++) {
            uint64_t w = sWE0[k * 8 + j];
            c0 = fma2(x2[0][k], w, c0);
            c1 = fma2(x2[1][k], w, c1);
        }
        h0[0][j] = relu2(c0); h0[1][j] = relu2(c1);
    }

    // ----- edge L1: 8 -> 16 -----
    uint64_t h1[2][16];
#pragma unroll
    for (int j = 0; j < 16; j++) {
        uint64_t c0 = sBE1[j], c1 = c0;
#pragma unroll
        for (int k = 0; k < 8; k++) {
            uint64_t w = sWE1[k * 16 + j];
            c0 = fma2(h0[0][k], w, c0);
            c1 = fma2(h0[1][k], w, c1);
        }
        h1[0][j] = relu2(c0); h1[1][j] = relu2(c1);
    }

    // ----- edge L2: 16 -> 32 -----
    uint64_t h2[2][32];
#pragma unroll 2
    for (int j = 0; j < 32; j++) {
        uint64_t c0 = sBE2[j], c1 = c0;
#pragma unroll
        for (int k = 0; k < 16; k++) {
            uint64_t w = sWE2[k * 32 + j];
            c0 = fma2(h1[0][k], w, c0);
            c1 = fma2(h1[1][k], w, c1);
        }
        h2[0][j] = relu2(c0); h2[1][j] = relu2(c1);
    }

    // ----- edge L3: 32 -> 64, streamed + vector scatter -----
    float* agg[4];
#pragma unroll
    for (int p = 0; p < 4; p++) agg[p] = g_agg + (size_t)lbl[p] * 64;

#pragma unroll 1
    for (int j4 = 0; j4 < 16; j4++) {
        float r[4][4];
#pragma unroll
        for (int jj = 0; jj < 4; jj++) {
            int j = j4 * 4 + jj;
            uint64_t c0 = sBE3[j], c1 = c0;
#pragma unroll
            for (int k = 0; k < 32; k++) {
                uint64_t w = sWE3[k * 64 + j];
                c0 = fma2(h2[0][k], w, c0);
                c1 = fma2(h2[1][k], w, c1);
            }
            c0 = mul2(relu2(c0), a2[0]);
            c1 = mul2(relu2(c1), a2[1]);
            float2 f0 = unpack2(c0), f1 = unpack2(c1);
            r[0][jj] = f0.x; r[1][jj] = f0.y;
            r[2][jj] = f1.x; r[3][jj] = f1.y;
        }
#pragma unroll
        for (int p = 0; p < 4; p++)
            if (ok[p]) red4(agg[p] + j4 * 4, r[p][0], r[p][1], r[p][2], r[p][3]);
    }
}

// ---------------------------------------------------------------------------
// Kernel 2: g_mid = relu(g_agg @ wo0 + bo0). 16 clusters/block, f32x2 pairs,
// transposed activation staging. Output blocked [c/16][k][c%16].
// ---------------------------------------------------------------------------
__global__ __launch_bounds__(256) void k_mid(
    const float* __restrict__ wo0, const float* __restrict__ bo0)
{
    __shared__ float sw[64 * 128];                 // 32 KB
    __shared__ float sb[128];
    __shared__ float saggT[64 * 16];               // [k][c] 4 KB

    const int t  = threadIdx.x;
    const int cb = blockIdx.x * 16;

    for (int i = t; i < 8192; i += 256) sw[i] = wo0[i];
    if (t < 128) sb[t] = bo0[t];
    {   // coalesced load of 16 rows x 64 floats, transpose into saggT
        int c  = t >> 4;          // 0..15
        int k4 = t & 15;          // 0..15
        float4 v = ((const float4*)g_agg)[(size_t)(cb + c) * 16 + k4];
        saggT[(k4 * 4 + 0) * 16 + c] = v.x;
        saggT[(k4 * 4 + 1) * 16 + c] = v.y;
        saggT[(k4 * 4 + 2) * 16 + c] = v.z;
        saggT[(k4 * 4 + 3) * 16 + c] = v.w;
    }
    __syncthreads();

    const int j    = t & 127;   // output col
    const int half = t >> 7;    // 0/1 -> cluster pairs half*4 .. half*4+3

    uint64_t acc[4];
    {
        float b = sb[j];
#pragma unroll
        for (int p = 0; p < 4; p++) acc[p] = pack2(b, b);
    }

#pragma unroll 4
    for (int k = 0; k < 64; k++) {
        float w = sw[k * 128 + j];
        uint64_t w2 = pack2(w, w);
        const uint64_t* row = (const uint64_t*)(saggT + k * 16) + half * 4;
#pragma unroll
        for (int p = 0; p < 4; p++)
            acc[p] = fma2(row[p], w2, acc[p]);
    }

    float* dst = g_mid + (size_t)blockIdx.x * 2048 + (size_t)j * 16 + half * 8;
#pragma unroll
    for (int p = 0; p < 4; p++) {
        float2 f = unpack2(acc[p]);
        f.x = fmaxf(f.x, 0.0f); f.y = fmaxf(f.y, 0.0f);
        ((float2*)dst)[p] = f;
    }
}

// ---------------------------------------------------------------------------
// Kernel 3: out = relu(g_mid @ wo1 + bo1). 128 threads, 16 clusters,
// 2 output cols/thread x 8 cluster-pairs -> LDS/FFMA2 = 9/16.
// ---------------------------------------------------------------------------
__global__ __launch_bounds__(128) void k_out(
    const float* __restrict__ wo1, const float* __restrict__ bo1,
    float* __restrict__ out)
{
    __shared__ float sw[32 * 256];                     // 32 KB weight chunk
    __shared__ __align__(16) uint64_t smid[128 * 8];   // [k][cpair]

    const int t  = threadIdx.x;
    const int cg = blockIdx.x;          // group of 16 clusters

    const uint64_t* gm = (const uint64_t*)(g_mid + (size_t)cg * 2048);
    for (int i = t; i < 1024; i += 128) smid[i] = gm[i];

    uint64_t acc0[8], acc1[8];
    {
        float2 b = *(const float2*)(bo1 + 2 * t);
#pragma unroll
        for (int p = 0; p < 8; p++) { acc0[p] = pack2(b.x, b.x); acc1[p] = pack2(b.y, b.y); }
    }

    for (int kb = 0; kb < 4; kb++) {
        __syncthreads();
        for (int i = t; i < 8192; i += 128) sw[i] = wo1[kb * 8192 + i];
        __syncthreads();

#pragma unroll 4
        for (int k = 0; k < 32; k++) {
            float2 w = *(const float2*)(sw + k * 256 + 2 * t);
            uint64_t w20 = pack2(w.x, w.x);
            uint64_t w21 = pack2(w.y, w.y);
            const uint64_t* mrow = smid + (kb * 32 + k) * 8;
#pragma unroll
            for (int p = 0; p < 8; p++) {
                uint64_t m = mrow[p];
                acc0[p] = fma2(m, w20, acc0[p]);
                acc1[p] = fma2(m, w21, acc1[p]);
            }
        }
    }

#pragma unroll
    for (int p = 0; p < 8; p++) {
        float2 fa = unpack2(acc0[p]);   // col 2t:   clusters (2p, 2p+1)
        float2 fb = unpack2(acc1[p]);   // col 2t+1: clusters (2p, 2p+1)
        float2 o0 = make_float2(fmaxf(fa.x, 0.0f), fmaxf(fb.x, 0.0f));
        float2 o1 = make_float2(fmaxf(fa.y, 0.0f), fmaxf(fb.y, 0.0f));
        *(float2*)(out + (size_t)(cg * 16 + 2 * p) * 256 + 2 * t)     = o0;
        *(float2*)(out + (size_t)(cg * 16 + 2 * p + 1) * 256 + 2 * t) = o1;
    }
}

// ---------------------------------------------------------------------------
extern "C" void kernel_launch(void* const* d_in, const int* in_sizes, int n_in,
                              void* d_out, int out_size)
{
    const float* pf     = (const float*)d_in[0];
    const int*   labels = (const int*)  d_in[1];
    const float* cc     = (const float*)d_in[2];
    const float* pts    = (const float*)d_in[3];
    const float* we0    = (const float*)d_in[4];
    const float* be0    = (const float*)d_in[5];
    const float* we1    = (const float*)d_in[6];
    const float* be1    = (const float*)d_in[7];
    const float* we2    = (const float*)d_in[8];
    const float* be2    = (const float*)d_in[9];
    const float* we3    = (const float*)d_in[10];
    const float* be3    = (const float*)d_in[11];
    const float* wa0    = (const float*)d_in[12];
    const float* ba0    = (const float*)d_in[13];
    const float* wa1    = (const float*)d_in[14];
    const float* ba1    = (const float*)d_in[15];
    const float* wo0    = (const float*)d_in[16];
    const float* bo0    = (const float*)d_in[17];
    const float* wo1    = (const float*)d_in[18];
    const float* bo1    = (const float*)d_in[19];
    float* out = (float*)d_out;

    k_zero<<<N_CLU * 64 / 4 / 256, 256>>>();
    k_point<<<(N_PTS + 511) / 512, 128>>>(pf, labels, cc, pts,
                                          we0, be0, we1, be1, we2, be2, we3, be3,
                                          wa0, ba0, wa1, ba1);
    k_mid<<<N_CLU / 16, 256>>>(wo0, bo0);
    k_out<<<N_CLU / 16, 128>>>(wo1, bo1, out);
}

// round 4
// speedup vs baseline: 1.7549x; 1.1166x over previous
#include <cuda_runtime.h>
#include <math.h>
#include <stdint.h>

#define N_PTS 2000000
#define N_CLU 65536

__device__ float g_agg[N_CLU * 64];     // segment-sum accumulator [C,64]
__device__ float g_mid[N_CLU * 128];    // blocked: [c/32][k=0..127][c%32]

// ---------------------------------------------------------------------------
// packed f32x2 helpers
// ---------------------------------------------------------------------------
__device__ __forceinline__ uint64_t pack2(float lo, float hi) {
    uint64_t r; asm("mov.b64 %0,{%1,%2};" : "=l"(r) : "f"(lo), "f"(hi)); return r;
}
__device__ __forceinline__ float2 unpack2(uint64_t v) {
    float2 r; asm("mov.b64 {%0,%1},%2;" : "=f"(r.x), "=f"(r.y) : "l"(v)); return r;
}
__device__ __forceinline__ uint64_t fma2(uint64_t a, uint64_t b, uint64_t c) {
    uint64_t d; asm("fma.rn.f32x2 %0,%1,%2,%3;" : "=l"(d) : "l"(a), "l"(b), "l"(c)); return d;
}
__device__ __forceinline__ uint64_t mul2(uint64_t a, uint64_t b) {
    uint64_t d; asm("mul.rn.f32x2 %0,%1,%2;" : "=l"(d) : "l"(a), "l"(b)); return d;
}
__device__ __forceinline__ uint64_t relu2(uint64_t v) {
    float2 f = unpack2(v);
    return pack2(fmaxf(f.x, 0.0f), fmaxf(f.y, 0.0f));
}
__device__ __forceinline__ void red4(float* p, float a, float b, float c, float d) {
    asm volatile("red.global.add.v4.f32 [%0], {%1,%2,%3,%4};"
                 :: "l"(p), "f"(a), "f"(b), "f"(c), "f"(d) : "memory");
}

// ---------------------------------------------------------------------------
// Kernel 0: zero the aggregation buffer
// ---------------------------------------------------------------------------
__global__ void k_zero() {
    int i = blockIdx.x * 256 + threadIdx.x;
    ((float4*)g_agg)[i] = make_float4(0.f, 0.f, 0.f, 0.f);
}

// ---------------------------------------------------------------------------
// Kernel 1: per-point MLPs + scatter. 4 points/thread as two f32x2 pairs;
// j-pair processing: one LDS.128 weight fetch feeds 4 FFMA2.
// ---------------------------------------------------------------------------
__global__ __launch_bounds__(128) void k_point(
    const float* __restrict__ pf, const int* __restrict__ labels,
    const float* __restrict__ cc, const float* __restrict__ pts,
    const float* __restrict__ we0, const float* __restrict__ be0,
    const float* __restrict__ we1, const float* __restrict__ be1,
    const float* __restrict__ we2, const float* __restrict__ be2,
    const float* __restrict__ we3, const float* __restrict__ be3,
    const float* __restrict__ wa0, const float* __restrict__ ba0,
    const float* __restrict__ wa1, const float* __restrict__ ba1)
{
    __shared__ __align__(16) uint64_t s[3730];
    uint64_t* sWE0 = s + 0;     // 88
    uint64_t* sBE0 = s + 88;    // 8
    uint64_t* sWE1 = s + 96;    // 128
    uint64_t* sBE1 = s + 224;   // 16
    uint64_t* sWE2 = s + 240;   // 512
    uint64_t* sBE2 = s + 752;   // 32
    uint64_t* sWE3 = s + 784;   // 2048
    uint64_t* sBE3 = s + 2832;  // 64
    uint64_t* sWA0 = s + 2896;  // 704
    uint64_t* sBA0 = s + 3600;  // 64
    uint64_t* sWA1 = s + 3664;  // 64
    uint64_t* sBA1 = s + 3728;  // 1

    const int t = threadIdx.x;
    {
        #define DUP(dst, src, n) for (int i = t; i < (n); i += 128) { float v = (src)[i]; (dst)[i] = pack2(v, v); }
        DUP(sWE0, we0, 88)   DUP(sBE0, be0, 8)
        DUP(sWE1, we1, 128)  DUP(sBE1, be1, 16)
        DUP(sWE2, we2, 512)  DUP(sBE2, be2, 32)
        DUP(sWE3, we3, 2048) DUP(sBE3, be3, 64)
        DUP(sWA0, wa0, 704)  DUP(sBA0, ba0, 64)
        DUP(sWA1, wa1, 64)   DUP(sBA1, ba1, 1)
        #undef DUP
    }
    __syncthreads();

    const int base = blockIdx.x * 512 + t;
    int  idx[4];
    bool ok[4];
#pragma unroll
    for (int p = 0; p < 4; p++) {
        idx[p] = base + p * 128;
        ok[p]  = (idx[p] < N_PTS);
        if (!ok[p]) idx[p] = 0;
    }

    uint64_t x2[2][11];
    int lbl[4];
#pragma unroll
    for (int q = 0; q < 2; q++) {
        int ia = idx[2 * q], ib = idx[2 * q + 1];
        const float4* pa = (const float4*)(pf + (size_t)ia * 8);
        const float4* pb = (const float4*)(pf + (size_t)ib * 8);
        float4 a0 = pa[0], a1 = pa[1], b0 = pb[0], b1 = pb[1];
        x2[q][0] = pack2(a0.x, b0.x); x2[q][1] = pack2(a0.y, b0.y);
        x2[q][2] = pack2(a0.z, b0.z); x2[q][3] = pack2(a0.w, b0.w);
        x2[q][4] = pack2(a1.x, b1.x); x2[q][5] = pack2(a1.y, b1.y);
        x2[q][6] = pack2(a1.z, b1.z); x2[q][7] = pack2(a1.w, b1.w);
        int la = labels[ia], lb = labels[ib];
        lbl[2 * q] = la; lbl[2 * q + 1] = lb;
#pragma unroll
        for (int k = 0; k < 3; k++)
            x2[q][8 + k] = pack2(cc[(size_t)la * 3 + k] - pts[(size_t)ia * 3 + k],
                                 cc[(size_t)lb * 3 + k] - pts[(size_t)ib * 3 + k]);
    }

    // ----- attention: j-pairs -----
    uint64_t aa0 = sBA1[0], aa1 = aa0;
#pragma unroll 2
    for (int j = 0; j < 64; j += 2) {
        ulonglong2 b = *(const ulonglong2*)&sBA0[j];
        uint64_t c00 = b.x, c01 = b.y, c10 = b.x, c11 = b.y;
#pragma unroll
        for (int k = 0; k < 11; k++) {
            ulonglong2 w = *(const ulonglong2*)&sWA0[k * 64 + j];
            c00 = fma2(x2[0][k], w.x, c00); c01 = fma2(x2[0][k], w.y, c01);
            c10 = fma2(x2[1][k], w.x, c10); c11 = fma2(x2[1][k], w.y, c11);
        }
        ulonglong2 w1 = *(const ulonglong2*)&sWA1[j];
        aa0 = fma2(relu2(c00), w1.x, aa0); aa0 = fma2(relu2(c01), w1.y, aa0);
        aa1 = fma2(relu2(c10), w1.x, aa1); aa1 = fma2(relu2(c11), w1.y, aa1);
    }
    uint64_t a2[2];
    {
        float2 v0 = unpack2(aa0), v1 = unpack2(aa1);
        a2[0] = pack2(1.0f / (1.0f + __expf(-v0.x)), 1.0f / (1.0f + __expf(-v0.y)));
        a2[1] = pack2(1.0f / (1.0f + __expf(-v1.x)), 1.0f / (1.0f + __expf(-v1.y)));
    }

    // ----- edge L0: 11 -> 8 -----
    uint64_t h0[2][8];
#pragma unroll
    for (int j = 0; j < 8; j += 2) {
        ulonglong2 b = *(const ulonglong2*)&sBE0[j];
        uint64_t c00 = b.x, c01 = b.y, c10 = b.x, c11 = b.y;
#pragma unroll
        for (int k = 0; k < 11; k++) {
            ulonglong2 w = *(const ulonglong2*)&sWE0[k * 8 + j];
            c00 = fma2(x2[0][k], w.x, c00); c01 = fma2(x2[0][k], w.y, c01);
            c10 = fma2(x2[1][k], w.x, c10); c11 = fma2(x2[1][k], w.y, c11);
        }
        h0[0][j] = relu2(c00); h0[0][j + 1] = relu2(c01);
        h0[1][j] = relu2(c10); h0[1][j + 1] = relu2(c11);
    }

    // ----- edge L1: 8 -> 16 -----
    uint64_t h1[2][16];
#pragma unroll
    for (int j = 0; j < 16; j += 2) {
        ulonglong2 b = *(const ulonglong2*)&sBE1[j];
        uint64_t c00 = b.x, c01 = b.y, c10 = b.x, c11 = b.y;
#pragma unroll
        for (int k = 0; k < 8; k++) {
            ulonglong2 w = *(const ulonglong2*)&sWE1[k * 16 + j];
            c00 = fma2(h0[0][k], w.x, c00); c01 = fma2(h0[0][k], w.y, c01);
            c10 = fma2(h0[1][k], w.x, c10); c11 = fma2(h0[1][k], w.y, c11);
        }
        h1[0][j] = relu2(c00); h1[0][j + 1] = relu2(c01);
        h1[1][j] = relu2(c10); h1[1][j + 1] = relu2(c11);
    }

    // ----- edge L2: 16 -> 32 -----
    uint64_t h2[2][32];
#pragma unroll 2
    for (int j = 0; j < 32; j += 2) {
        ulonglong2 b = *(const ulonglong2*)&sBE2[j];
        uint64_t c00 = b.x, c01 = b.y, c10 = b.x, c11 = b.y;
#pragma unroll
        for (int k = 0; k < 16; k++) {
            ulonglong2 w = *(const ulonglong2*)&sWE2[k * 32 + j];
            c00 = fma2(h1[0][k], w.x, c00); c01 = fma2(h1[0][k], w.y, c01);
            c10 = fma2(h1[1][k], w.x, c10); c11 = fma2(h1[1][k], w.y, c11);
        }
        h2[0][j] = relu2(c00); h2[0][j + 1] = relu2(c01);
        h2[1][j] = relu2(c10); h2[1][j + 1] = relu2(c11);
    }

    // ----- edge L3: 32 -> 64, streamed in groups of 4 j + vector scatter -----
    float* agg[4];
#pragma unroll
    for (int p = 0; p < 4; p++) agg[p] = g_agg + (size_t)lbl[p] * 64;

#pragma unroll 1
    for (int j4 = 0; j4 < 16; j4++) {
        float r[4][4];
#pragma unroll
        for (int jj = 0; jj < 4; jj += 2) {
            int j = j4 * 4 + jj;
            ulonglong2 b = *(const ulonglong2*)&sBE3[j];
            uint64_t c00 = b.x, c01 = b.y, c10 = b.x, c11 = b.y;
#pragma unroll
            for (int k = 0; k < 32; k++) {
                ulonglong2 w = *(const ulonglong2*)&sWE3[k * 64 + j];
                c00 = fma2(h2[0][k], w.x, c00); c01 = fma2(h2[0][k], w.y, c01);
                c10 = fma2(h2[1][k], w.x, c10); c11 = fma2(h2[1][k], w.y, c11);
            }
            c00 = mul2(relu2(c00), a2[0]); c01 = mul2(relu2(c01), a2[0]);
            c10 = mul2(relu2(c10), a2[1]); c11 = mul2(relu2(c11), a2[1]);
            float2 f00 = unpack2(c00), f01 = unpack2(c01);
            float2 f10 = unpack2(c10), f11 = unpack2(c11);
            r[0][jj] = f00.x; r[0][jj + 1] = f01.x;
            r[1][jj] = f00.y; r[1][jj + 1] = f01.y;
            r[2][jj] = f10.x; r[2][jj + 1] = f11.x;
            r[3][jj] = f10.y; r[3][jj + 1] = f11.y;
        }
#pragma unroll
        for (int p = 0; p < 4; p++)
            if (ok[p]) red4(agg[p] + j4 * 4, r[p][0], r[p][1], r[p][2], r[p][3]);
    }
}

// ---------------------------------------------------------------------------
// Kernel 2: g_mid = relu(g_agg @ wo0 + bo0). 16 clusters/block.
// Output blocked [c/32][k][c%32].
// ---------------------------------------------------------------------------
__global__ __launch_bounds__(256) void k_mid(
    const float* __restrict__ wo0, const float* __restrict__ bo0)
{
    __shared__ float sw[64 * 128];                     // 32 KB
    __shared__ float sb[128];
    __shared__ __align__(16) float saggT[64 * 16];     // [k][c] 4 KB

    const int t  = threadIdx.x;
    const int cb = blockIdx.x * 16;

    for (int i = t; i < 8192; i += 256) sw[i] = wo0[i];
    if (t < 128) sb[t] = bo0[t];
    {
        int c  = t >> 4;
        int k4 = t & 15;
        float4 v = ((const float4*)g_agg)[(size_t)(cb + c) * 16 + k4];
        saggT[(k4 * 4 + 0) * 16 + c] = v.x;
        saggT[(k4 * 4 + 1) * 16 + c] = v.y;
        saggT[(k4 * 4 + 2) * 16 + c] = v.z;
        saggT[(k4 * 4 + 3) * 16 + c] = v.w;
    }
    __syncthreads();

    const int j    = t & 127;
    const int half = t >> 7;

    uint64_t acc[4];
    {
        float b = sb[j];
#pragma unroll
        for (int p = 0; p < 4; p++) acc[p] = pack2(b, b);
    }

#pragma unroll 4
    for (int k = 0; k < 64; k++) {
        float w = sw[k * 128 + j];
        uint64_t w2 = pack2(w, w);
        const uint64_t* row = (const uint64_t*)(saggT + k * 16) + half * 4;
        ulonglong2 m0 = *(const ulonglong2*)(row);
        ulonglong2 m1 = *(const ulonglong2*)(row + 2);
        acc[0] = fma2(m0.x, w2, acc[0]);
        acc[1] = fma2(m0.y, w2, acc[1]);
        acc[2] = fma2(m1.x, w2, acc[2]);
        acc[3] = fma2(m1.y, w2, acc[3]);
    }

    // blocked [c/32][k][c%32]
    const int group = blockIdx.x >> 1;
    const int lane0 = (blockIdx.x & 1) * 16 + half * 8;
    float* dst = g_mid + (size_t)group * 4096 + (size_t)j * 32 + lane0;
#pragma unroll
    for (int p = 0; p < 4; p++) {
        float2 f = unpack2(acc[p]);
        f.x = fmaxf(f.x, 0.0f); f.y = fmaxf(f.y, 0.0f);
        ((float2*)dst)[p] = f;
    }
}

// ---------------------------------------------------------------------------
// Kernel 3: out = relu(g_mid @ wo1 + bo1). 32 clusters/block, 128 threads.
// Thread = 4 cols x 8 cluster-pairs. Weights LDG.128 from L2, acts LDS.128.
// ---------------------------------------------------------------------------
__global__ __launch_bounds__(128) void k_out(
    const float* __restrict__ wo1, const float* __restrict__ bo1,
    float* __restrict__ out)
{
    __shared__ __align__(16) uint64_t smid[128 * 16];   // [k][pair] 16 KB

    const int t    = threadIdx.x;
    const int cg   = t & 63;     // col group: cols 4cg..4cg+3
    const int half = t >> 6;     // pairs half*8 .. half*8+7 (warp-uniform)
    const int grp  = blockIdx.x; // 32 clusters

    const uint64_t* gm = (const uint64_t*)(g_mid + (size_t)grp * 4096);
    for (int i = t; i < 2048; i += 128) smid[i] = gm[i];
    __syncthreads();

    uint64_t acc[4][8];
    {
        float4 b = ((const float4*)bo1)[cg];
#pragma unroll
        for (int p = 0; p < 8; p++) {
            acc[0][p] = pack2(b.x, b.x); acc[1][p] = pack2(b.y, b.y);
            acc[2][p] = pack2(b.z, b.z); acc[3][p] = pack2(b.w, b.w);
        }
    }

    const float4* w4p = (const float4*)wo1;
#pragma unroll 4
    for (int k = 0; k < 128; k++) {
        float4 w = w4p[k * 64 + cg];
        uint64_t wd0 = pack2(w.x, w.x), wd1 = pack2(w.y, w.y);
        uint64_t wd2 = pack2(w.z, w.z), wd3 = pack2(w.w, w.w);
        const uint64_t* mrow = smid + k * 16 + half * 8;
        ulonglong2 m0 = *(const ulonglong2*)(mrow);
        ulonglong2 m1 = *(const ulonglong2*)(mrow + 2);
        ulonglong2 m2 = *(const ulonglong2*)(mrow + 4);
        ulonglong2 m3 = *(const ulonglong2*)(mrow + 6);
        uint64_t m[8] = {m0.x, m0.y, m1.x, m1.y, m2.x, m2.y, m3.x, m3.y};
#pragma unroll
        for (int p = 0; p < 8; p++) {
            acc[0][p] = fma2(m[p], wd0, acc[0][p]);
            acc[1][p] = fma2(m[p], wd1, acc[1][p]);
            acc[2][p] = fma2(m[p], wd2, acc[2][p]);
            acc[3][p] = fma2(m[p], wd3, acc[3][p]);
        }
    }

#pragma unroll
    for (int p = 0; p < 8; p++) {
        int pp = half * 8 + p;
        int c0 = grp * 32 + 2 * pp;
        float2 f0 = unpack2(acc[0][p]), f1 = unpack2(acc[1][p]);
        float2 f2 = unpack2(acc[2][p]), f3 = unpack2(acc[3][p]);
        float4 o0 = make_float4(fmaxf(f0.x, 0.f), fmaxf(f1.x, 0.f),
                                fmaxf(f2.x, 0.f), fmaxf(f3.x, 0.f));
        float4 o1 = make_float4(fmaxf(f0.y, 0.f), fmaxf(f1.y, 0.f),
                                fmaxf(f2.y, 0.f), fmaxf(f3.y, 0.f));
        *(float4*)(out + (size_t)c0 * 256 + 4 * cg)       = o0;
        *(float4*)(out + (size_t)(c0 + 1) * 256 + 4 * cg) = o1;
    }
}

// ---------------------------------------------------------------------------
extern "C" void kernel_launch(void* const* d_in, const int* in_sizes, int n_in,
                              void* d_out, int out_size)
{
    const float* pf     = (const float*)d_in[0];
    const int*   labels = (const int*)  d_in[1];
    const float* cc     = (const float*)d_in[2];
    const float* pts    = (const float*)d_in[3];
    const float* we0    = (const float*)d_in[4];
    const float* be0    = (const float*)d_in[5];
    const float* we1    = (const float*)d_in[6];
    const float* be1    = (const float*)d_in[7];
    const float* we2    = (const float*)d_in[8];
    const float* be2    = (const float*)d_in[9];
    const float* we3    = (const float*)d_in[10];
    const float* be3    = (const float*)d_in[11];
    const float* wa0    = (const float*)d_in[12];
    const float* ba0    = (const float*)d_in[13];
    const float* wa1    = (const float*)d_in[14];
    const float* ba1    = (const float*)d_in[15];
    const float* wo0    = (const float*)d_in[16];
    const float* bo0    = (const float*)d_in[17];
    const float* wo1    = (const float*)d_in[18];
    const float* bo1    = (const float*)d_in[19];
    float* out = (float*)d_out;

    k_zero<<<N_CLU * 64 / 4 / 256, 256>>>();
    k_point<<<(N_PTS + 511) / 512, 128>>>(pf, labels, cc, pts,
                                          we0, be0, we1, be1, we2, be2, we3, be3,
                                          wa0, ba0, wa1, ba1);
    k_mid<<<N_CLU / 16, 256>>>(wo0, bo0);
    k_out<<<N_CLU / 32, 128>>>(wo1, bo1, out);
}